// round 3
// baseline (speedup 1.0000x reference)
#include <cuda_runtime.h>
#include <math.h>

#define BATCH 16
#define H     1024
#define W     1024
#define HS    512
#define WS    512
#define HC    256
#define WC    256
#define C1    32
#define KP    32
#define CROPSZ 160

// ---- scratch (static __device__ per allocation rules) ----
__device__ float g_tmp[BATCH * H * WS];              // 32 MB: horizontally resized
__device__ float g_img[BATCH * HS * WS];             // 16 MB: resized 512x512
__device__ float g_h1[(size_t)BATCH * HC * WC * C1]; // 134 MB: conv1 out, HWC
__device__ float g_cms[BATCH * HC * WC];             // 4 MB: confmaps
__device__ float g_nms[BATCH * HC * WC];             // 4 MB: NMS-thresholded scores
__device__ float g_val[BATCH * KP];
__device__ int   g_idx[BATCH * KP];
__device__ float g_cx[BATCH * KP];
__device__ float g_cy[BATCH * KP];
__device__ int   g_vld[BATCH * KP];

// output layout (flat concat, f32): crops | crop_offsets | centroid_vals | valid
#define OFF_OFFS  (BATCH * KP * CROPSZ * CROPSZ)          // 13107200
#define OFF_VALS  (OFF_OFFS + BATCH * KP * 2)             // 13108224
#define OFF_VALID (OFF_VALS + BATCH * KP)                 // 13108736

// ============================================================
// 1) antialiased bilinear x0.5 resize, separable 4-tap
//    taps at 2i-1..2i+2, raw weights {.25,.75,.75,.25}, renormalized at edges
// ============================================================
__global__ void __launch_bounds__(256) k_resize_h(const float* __restrict__ in) {
    int i = blockIdx.x * blockDim.x + threadIdx.x;   // over BATCH*H*WS
    if (i >= BATCH * H * WS) return;
    int xo = i % WS;
    int y  = (i / WS) % H;
    int b  = i / (WS * H);
    const float wt0 = 0.25f, wt1 = 0.75f;
    int base = 2 * xo - 1;
    const float* row = in + ((size_t)b * H + y) * W;
    float acc = 0.f, wsum = 0.f;
    {
        int x = base;     if (x >= 0 && x < W) { acc += wt0 * row[x]; wsum += wt0; }
        x = base + 1;     if (x >= 0 && x < W) { acc += wt1 * row[x]; wsum += wt1; }
        x = base + 2;     if (x >= 0 && x < W) { acc += wt1 * row[x]; wsum += wt1; }
        x = base + 3;     if (x >= 0 && x < W) { acc += wt0 * row[x]; wsum += wt0; }
    }
    g_tmp[i] = acc / wsum;
}

__global__ void __launch_bounds__(256) k_resize_v() {
    int i = blockIdx.x * blockDim.x + threadIdx.x;   // over BATCH*HS*WS
    if (i >= BATCH * HS * WS) return;
    int x  = i % WS;
    int yo = (i / WS) % HS;
    int b  = i / (WS * HS);
    const float wt0 = 0.25f, wt1 = 0.75f;
    int base = 2 * yo - 1;
    const float* col = g_tmp + (size_t)b * H * WS + x;
    float acc = 0.f, wsum = 0.f;
    {
        int y = base;     if (y >= 0 && y < H) { acc += wt0 * col[(size_t)y * WS]; wsum += wt0; }
        y = base + 1;     if (y >= 0 && y < H) { acc += wt1 * col[(size_t)y * WS]; wsum += wt1; }
        y = base + 2;     if (y >= 0 && y < H) { acc += wt1 * col[(size_t)y * WS]; wsum += wt1; }
        y = base + 3;     if (y >= 0 && y < H) { acc += wt0 * col[(size_t)y * WS]; wsum += wt0; }
    }
    g_img[i] = acc / wsum;
}

// ============================================================
// 2) conv1: 5x5 stride 2 SAME (pad 1,2), 1->32 ch, +bias, relu
// ============================================================
__global__ void __launch_bounds__(256) k_conv1(const float* __restrict__ w1,
                                               const float* __restrict__ b1) {
    __shared__ float4 sw[25 * 8];   // [tap][c4]
    __shared__ float4 sbias[8];
    int tid = threadIdx.x;
    if (tid < 200) sw[tid] = ((const float4*)w1)[tid];
    if (tid < 8)   sbias[tid] = ((const float4*)b1)[tid];
    __syncthreads();

    int i = blockIdx.x * blockDim.x + tid;           // over BATCH*HC*WC
    if (i >= BATCH * HC * WC) return;
    int ox = i % WC;
    int oy = (i / WC) % HC;
    int b  = i / (WC * HC);

    float inv[25];
    #pragma unroll
    for (int ky = 0; ky < 5; ky++) {
        int iy = 2 * oy - 1 + ky;
        #pragma unroll
        for (int kx = 0; kx < 5; kx++) {
            int ix = 2 * ox - 1 + kx;
            inv[ky * 5 + kx] = (iy >= 0 && iy < HS && ix >= 0 && ix < WS)
                ? g_img[((size_t)b * HS + iy) * WS + ix] : 0.f;
        }
    }

    float4 acc[8];
    #pragma unroll
    for (int c4 = 0; c4 < 8; c4++) acc[c4] = sbias[c4];

    #pragma unroll
    for (int t = 0; t < 25; t++) {
        float v = inv[t];
        #pragma unroll
        for (int c4 = 0; c4 < 8; c4++) {
            float4 w = sw[t * 8 + c4];
            acc[c4].x = fmaf(v, w.x, acc[c4].x);
            acc[c4].y = fmaf(v, w.y, acc[c4].y);
            acc[c4].z = fmaf(v, w.z, acc[c4].z);
            acc[c4].w = fmaf(v, w.w, acc[c4].w);
        }
    }

    float4* outp = (float4*)(g_h1 + (size_t)i * C1);
    #pragma unroll
    for (int c4 = 0; c4 < 8; c4++) {
        float4 a = acc[c4];
        a.x = fmaxf(a.x, 0.f); a.y = fmaxf(a.y, 0.f);
        a.z = fmaxf(a.z, 0.f); a.w = fmaxf(a.w, 0.f);
        outp[c4] = a;
    }
}

// ============================================================
// 3) conv2: 5x5 stride 1 SAME (pad 2), 32->1 ch, +bias, sigmoid
//    16x8 output tile, shared [c4][y][x] float4 layout
// ============================================================
__global__ void __launch_bounds__(128) k_conv2(const float* __restrict__ w2,
                                               const float* __restrict__ b2) {
    __shared__ float4 s_t[8][12][20];   // [c4][py 0..11][px 0..19]
    __shared__ float4 sw2[25 * 8];      // [tap][c4]
    int tid = threadIdx.x;              // 128 threads
    int bx = blockIdx.x;                // 16 tiles of 16 cols
    int by = blockIdx.y;                // 32 tiles of 8 rows
    int b  = blockIdx.z;

    if (tid < 128) {
        sw2[tid] = ((const float4*)w2)[tid];
        if (tid < 72) sw2[128 + tid] = ((const float4*)w2)[128 + tid];
    }

    const float4* hp = (const float4*)g_h1;
    #pragma unroll
    for (int it = 0; it < 15; it++) {
        int e  = it * 128 + tid;        // < 1920
        int c4 = e & 7;
        int px = (e >> 3) % 20;
        int py = e / 160;
        int gy = by * 8 + py - 2;
        int gx = bx * 16 + px - 2;
        float4 v = make_float4(0.f, 0.f, 0.f, 0.f);
        if (gy >= 0 && gy < HC && gx >= 0 && gx < WC)
            v = hp[(((size_t)b * HC + gy) * WC + gx) * 8 + c4];
        s_t[c4][py][px] = v;
    }
    __syncthreads();

    int tx = tid & 15;
    int ty = tid >> 4;                  // 0..7
    float acc = 0.f;
    #pragma unroll
    for (int ky = 0; ky < 5; ky++) {
        #pragma unroll
        for (int kx = 0; kx < 5; kx++) {
            #pragma unroll
            for (int c4 = 0; c4 < 8; c4++) {
                float4 v = s_t[c4][ty + ky][tx + kx];
                float4 w = sw2[(ky * 5 + kx) * 8 + c4];
                acc = fmaf(v.x, w.x, acc);
                acc = fmaf(v.y, w.y, acc);
                acc = fmaf(v.z, w.z, acc);
                acc = fmaf(v.w, w.w, acc);
            }
        }
    }
    float z = acc + __ldg(b2);
    float s = 1.f / (1.f + expf(-z));
    int oy = by * 8 + ty;
    int ox = bx * 16 + tx;
    g_cms[((size_t)b * HC + oy) * WC + ox] = s;
}

// ============================================================
// 4a) 3x3 NMS + threshold -> global score buffer
// ============================================================
__global__ void __launch_bounds__(256) k_nms() {
    int i = blockIdx.x * blockDim.x + threadIdx.x;   // over BATCH*HC*WC
    if (i >= BATCH * HC * WC) return;
    int p = i & (HC * WC - 1);
    int b = i >> 16;
    int y = p >> 8, x = p & 255;
    const float* cm = g_cms + (size_t)b * HC * WC;
    float v = cm[p];
    float mx = v;
    #pragma unroll
    for (int dy = -1; dy <= 1; dy++) {
        int yy = y + dy;
        if (yy < 0 || yy >= HC) continue;
        #pragma unroll
        for (int dx = -1; dx <= 1; dx++) {
            int xx = x + dx;
            if (xx < 0 || xx >= WC) continue;
            mx = fmaxf(mx, cm[yy * WC + xx]);
        }
    }
    g_nms[i] = (v >= mx && v > 0.2f) ? v : -INFINITY;
}

// ============================================================
// 4b) exact top-32 per sample (jax tie-break: val desc, idx asc)
//     one block (1024 thr)/sample; thread state = one 64-bit key register
// ============================================================
__device__ __forceinline__ unsigned int f2ord(float v) {
    unsigned int u = __float_as_uint(v);
    return (u & 0x80000000u) ? ~u : (u | 0x80000000u);
}
__device__ __forceinline__ float ord2f(unsigned int u) {
    unsigned int bits = (u & 0x80000000u) ? (u ^ 0x80000000u) : ~u;
    return __uint_as_float(bits);
}
__device__ __forceinline__ unsigned long long mk_key(float v, unsigned p) {
    return ((unsigned long long)f2ord(v) << 32) |
           (unsigned long long)(0xFFFFFFFFu - p);
}

__global__ void __launch_bounds__(1024) k_topk() {
    int b = blockIdx.x;
    int t = threadIdx.x;                // 0..1023
    float* nms = g_nms + (size_t)b * HC * WC;

    unsigned long long mybest = 0;
    #pragma unroll 4
    for (int s = 0; s < 64; s++) {
        unsigned p = s * 1024 + t;
        unsigned long long key = mk_key(nms[p], p);
        if (key > mybest) mybest = key;
    }

    __shared__ unsigned long long warpbest[32];
    __shared__ unsigned long long winner;
    int lane = t & 31, wid = t >> 5;

    for (int k = 0; k < KP; k++) {
        unsigned long long v = mybest;
        #pragma unroll
        for (int off = 16; off > 0; off >>= 1) {
            unsigned long long o = __shfl_xor_sync(0xFFFFFFFFu, v, off);
            if (o > v) v = o;
        }
        if (lane == 0) warpbest[wid] = v;
        __syncthreads();
        if (t < 32) {
            unsigned long long bb = warpbest[t];
            #pragma unroll
            for (int off = 16; off > 0; off >>= 1) {
                unsigned long long o = __shfl_xor_sync(0xFFFFFFFFu, bb, off);
                if (o > bb) bb = o;
            }
            if (t == 0) winner = bb;
        }
        __syncthreads();
        unsigned long long wk = winner;
        unsigned int widx = 0xFFFFFFFFu - (unsigned int)(wk & 0xFFFFFFFFu);
        if (t == 0) {
            g_val[b * KP + k] = ord2f((unsigned int)(wk >> 32));
            g_idx[b * KP + k] = (int)widx;
        }
        if ((widx & 1023u) == (unsigned)t) {
            nms[widx] = -INFINITY;
            unsigned long long nb = 0;
            for (int s = 0; s < 64; s++) {
                unsigned p = s * 1024 + t;
                unsigned long long key = mk_key(nms[p], p);
                if (key > nb) nb = key;
            }
            mybest = nb;
        }
        __syncthreads();
    }
}

// ============================================================
// 5) integral refinement + centroid outputs
// ============================================================
__global__ void __launch_bounds__(512) k_refine(float* __restrict__ out) {
    int i = blockIdx.x * blockDim.x + threadIdx.x;   // 512
    if (i >= BATCH * KP) return;
    int b = i / KP;
    float v = g_val[i];
    int idx = g_idx[i];
    int valid = isfinite(v) ? 1 : 0;
    int py = idx >> 8, px = idx & 255;
    const float* cm = g_cms + (size_t)b * HC * WC;

    float gv = 1e-12f, sx = 0.f, sy = 0.f;
    #pragma unroll
    for (int dy = -2; dy <= 2; dy++) {
        int y = py + dy;
        if (y < 0 || y >= HC) continue;
        #pragma unroll
        for (int dx = -2; dx <= 2; dx++) {
            int x = px + dx;
            if (x < 0 || x >= WC) continue;
            float p = cm[y * WC + x];
            gv += p;
            sx += p * (float)dx;
            sy += p * (float)dy;
        }
    }
    float dxo = sx / gv, dyo = sy / gv;
    float cx = ((float)px + dxo) * 4.0f;   // CM_STRIDE/SCALE = 2/0.5
    float cy = ((float)py + dyo) * 4.0f;
    if (!valid) { cx = 80.f; cy = 80.f; }
    float cvv = valid ? v : 0.f;

    g_cx[i] = cx; g_cy[i] = cy; g_vld[i] = valid;
    out[OFF_OFFS + i * 2 + 0] = cx - 80.f;
    out[OFF_OFFS + i * 2 + 1] = cy - 80.f;
    out[OFF_VALS + i] = cvv;
    out[OFF_VALID + i] = valid ? 1.f : 0.f;
}

// ============================================================
// 6) 160x160 bilinear crops from the full image (extrap 0, valid mask)
// ============================================================
__global__ void __launch_bounds__(256) k_crop(const float* __restrict__ img,
                                              float* __restrict__ out) {
    int bk  = blockIdx.y;                               // 0..511
    int pix = blockIdx.x * blockDim.x + threadIdx.x;    // 0..25599
    if (pix >= CROPSZ * CROPSZ) return;
    float* o = out + (size_t)bk * CROPSZ * CROPSZ + pix;
    if (!g_vld[bk]) { *o = 0.f; return; }

    int b = bk / KP;
    float cx = g_cx[bk], cy = g_cy[bk];
    int yy = pix / CROPSZ, xx = pix % CROPSZ;
    float syf = cy - 79.5f + (float)yy;
    float sxf = cx - 79.5f + (float)xx;
    float y0 = floorf(syf), x0 = floorf(sxf);
    float wy = syf - y0,   wx = sxf - x0;
    int iy0 = min(max((int)y0, 0), H - 1);
    int iy1 = min(max((int)y0 + 1, 0), H - 1);
    int ix0 = min(max((int)x0, 0), W - 1);
    int ix1 = min(max((int)x0 + 1, 0), W - 1);
    const float* im = img + (size_t)b * H * W;
    float a  = __ldg(&im[(size_t)iy0 * W + ix0]);
    float bb = __ldg(&im[(size_t)iy0 * W + ix1]);
    float c  = __ldg(&im[(size_t)iy1 * W + ix0]);
    float d  = __ldg(&im[(size_t)iy1 * W + ix1]);
    float top = a * (1.f - wx) + bb * wx;
    float bot = c * (1.f - wx) + d * wx;
    float r = top * (1.f - wy) + bot * wy;
    bool inr = (syf >= 0.f) && (syf <= (float)(H - 1)) &&
               (sxf >= 0.f) && (sxf <= (float)(W - 1));
    *o = inr ? r : 0.f;
}

// ============================================================
extern "C" void kernel_launch(void* const* d_in, const int* in_sizes, int n_in,
                              void* d_out, int out_size) {
    const float* full = (const float*)d_in[0];
    const float* w1   = (const float*)d_in[1];
    const float* b1   = (const float*)d_in[2];
    const float* w2   = (const float*)d_in[3];
    const float* b2   = (const float*)d_in[4];
    float* out = (float*)d_out;

    int n;
    n = BATCH * H * WS;   k_resize_h<<<(n + 255) / 256, 256>>>(full);
    n = BATCH * HS * WS;  k_resize_v<<<(n + 255) / 256, 256>>>();
    n = BATCH * HC * WC;  k_conv1<<<(n + 255) / 256, 256>>>(w1, b1);
    k_conv2<<<dim3(WC / 16, HC / 8, BATCH), 128>>>(w2, b2);
    n = BATCH * HC * WC;  k_nms<<<(n + 255) / 256, 256>>>();
    k_topk<<<BATCH, 1024>>>();
    k_refine<<<1, 512>>>(out);
    k_crop<<<dim3((CROPSZ * CROPSZ + 255) / 256, BATCH * KP), 256>>>(full, out);
}

// round 5
// speedup vs baseline: 1.1519x; 1.1519x over previous
#include <cuda_runtime.h>
#include <math.h>

#define BATCH 16
#define H     1024
#define W     1024
#define HS    512
#define WS    512
#define HC    256
#define WC    256
#define C1    32
#define KP    32
#define CROPSZ 160

// ---- scratch (static __device__ per allocation rules) ----
__device__ float g_tmp[BATCH * H * WS];              // 32 MB: horizontally resized
__device__ float g_img[BATCH * HS * WS];             // 16 MB: resized 512x512
__device__ float g_h1[(size_t)BATCH * C1 * HC * WC]; // 134 MB: conv1 out, CHW planes
__device__ float g_cms[BATCH * HC * WC];             // 4 MB: confmaps
__device__ float g_nms[BATCH * HC * WC];             // 4 MB: NMS-thresholded scores
__device__ float g_val[BATCH * KP];
__device__ int   g_idx[BATCH * KP];
__device__ float g_cx[BATCH * KP];
__device__ float g_cy[BATCH * KP];
__device__ int   g_vld[BATCH * KP];

// output layout (flat concat, f32): crops | crop_offsets | centroid_vals | valid
#define OFF_OFFS  (BATCH * KP * CROPSZ * CROPSZ)          // 13107200
#define OFF_VALS  (OFF_OFFS + BATCH * KP * 2)             // 13108224
#define OFF_VALID (OFF_VALS + BATCH * KP)                 // 13108736

// ============================================================
// 1) antialiased bilinear x0.5 resize, separable 4-tap
// ============================================================
__global__ void __launch_bounds__(256) k_resize_h(const float* __restrict__ in) {
    int i = blockIdx.x * blockDim.x + threadIdx.x;   // over BATCH*H*WS
    if (i >= BATCH * H * WS) return;
    int xo = i % WS;
    int y  = (i / WS) % H;
    int b  = i / (WS * H);
    const float wt0 = 0.25f, wt1 = 0.75f;
    int base = 2 * xo - 1;
    const float* row = in + ((size_t)b * H + y) * W;
    float acc = 0.f, wsum = 0.f;
    {
        int x = base;     if (x >= 0 && x < W) { acc += wt0 * row[x]; wsum += wt0; }
        x = base + 1;     if (x >= 0 && x < W) { acc += wt1 * row[x]; wsum += wt1; }
        x = base + 2;     if (x >= 0 && x < W) { acc += wt1 * row[x]; wsum += wt1; }
        x = base + 3;     if (x >= 0 && x < W) { acc += wt0 * row[x]; wsum += wt0; }
    }
    g_tmp[i] = acc / wsum;
}

__global__ void __launch_bounds__(256) k_resize_v() {
    int i = blockIdx.x * blockDim.x + threadIdx.x;   // over BATCH*HS*WS
    if (i >= BATCH * HS * WS) return;
    int x  = i % WS;
    int yo = (i / WS) % HS;
    int b  = i / (WS * HS);
    const float wt0 = 0.25f, wt1 = 0.75f;
    int base = 2 * yo - 1;
    const float* col = g_tmp + (size_t)b * H * WS + x;
    float acc = 0.f, wsum = 0.f;
    {
        int y = base;     if (y >= 0 && y < H) { acc += wt0 * col[(size_t)y * WS]; wsum += wt0; }
        y = base + 1;     if (y >= 0 && y < H) { acc += wt1 * col[(size_t)y * WS]; wsum += wt1; }
        y = base + 2;     if (y >= 0 && y < H) { acc += wt1 * col[(size_t)y * WS]; wsum += wt1; }
        y = base + 3;     if (y >= 0 && y < H) { acc += wt0 * col[(size_t)y * WS]; wsum += wt0; }
    }
    g_img[i] = acc / wsum;
}

// ============================================================
// 2) conv1: 5x5 stride 2 SAME (pad 1,2), 1->32 ch, +bias, relu
//    f32x2 packed FMA over channel pairs; output CHW planes
// ============================================================
__device__ __forceinline__ unsigned long long pack2(float a, float b) {
    unsigned long long r;
    asm("mov.b64 %0, {%1, %2};" : "=l"(r) : "r"(__float_as_uint(a)), "r"(__float_as_uint(b)));
    return r;
}
__device__ __forceinline__ void unpack2(unsigned long long v, float& a, float& b) {
    unsigned int lo, hi;
    asm("mov.b64 {%0, %1}, %2;" : "=r"(lo), "=r"(hi) : "l"(v));
    a = __uint_as_float(lo); b = __uint_as_float(hi);
}
__device__ __forceinline__ void ffma2(unsigned long long& acc,
                                      unsigned long long v, unsigned long long w) {
    asm("fma.rn.f32x2 %0, %1, %2, %3;" : "=l"(acc) : "l"(v), "l"(w), "l"(acc));
}

__global__ void __launch_bounds__(256) k_conv1(const float* __restrict__ w1,
                                               const float* __restrict__ b1) {
    __shared__ unsigned long long swp[25 * 16];  // [tap][chpair] = 400 u64
    __shared__ unsigned long long sbp[16];
    int tid = threadIdx.x;
    // 400 u64 with 256 threads: two passes (BUGFIX from round 4)
    swp[tid % 400 == tid ? tid : tid] = swp[0]; // no-op placeholder removed below
    if (tid < 256)      swp[tid]       = ((const unsigned long long*)w1)[tid];
    if (tid < 144)      swp[256 + tid] = ((const unsigned long long*)w1)[256 + tid];
    if (tid < 16)       sbp[tid]       = ((const unsigned long long*)b1)[tid];
    __syncthreads();

    int i = blockIdx.x * blockDim.x + tid;           // over BATCH*HC*WC
    if (i >= BATCH * HC * WC) return;
    int ox = i % WC;
    int oy = (i / WC) % HC;
    int b  = i / (WC * HC);

    float inv[25];
    #pragma unroll
    for (int ky = 0; ky < 5; ky++) {
        int iy = 2 * oy - 1 + ky;
        #pragma unroll
        for (int kx = 0; kx < 5; kx++) {
            int ix = 2 * ox - 1 + kx;
            inv[ky * 5 + kx] = (iy >= 0 && iy < HS && ix >= 0 && ix < WS)
                ? g_img[((size_t)b * HS + iy) * WS + ix] : 0.f;
        }
    }

    unsigned long long acc[16];
    #pragma unroll
    for (int j = 0; j < 16; j++) acc[j] = sbp[j];

    #pragma unroll
    for (int t = 0; t < 25; t++) {
        unsigned long long vv = pack2(inv[t], inv[t]);
        #pragma unroll
        for (int j = 0; j < 16; j++) ffma2(acc[j], vv, swp[t * 16 + j]);
    }

    // relu + store to CHW planes (coalesced per channel across warp)
    size_t pix = (size_t)oy * WC + ox;
    #pragma unroll
    for (int j = 0; j < 16; j++) {
        float a, c;
        unpack2(acc[j], a, c);
        a = fmaxf(a, 0.f); c = fmaxf(c, 0.f);
        g_h1[((size_t)(b * C1 + 2 * j)     * HC * WC) + pix] = a;
        g_h1[((size_t)(b * C1 + 2 * j + 1) * HC * WC) + pix] = c;
    }
}

// ============================================================
// 3) conv2: 5x5 stride 1 SAME (pad 2), 32->1 ch, +bias, sigmoid
//    CHW planes; 4-channel chunks staged in shared; 4x2 outputs/thread
// ============================================================
#define TX 128
#define TY 16
#define CCH 4
#define ROWF 136                       // padded row: 132 used floats

__global__ void __launch_bounds__(256) k_conv2(const float* __restrict__ w2,
                                               const float* __restrict__ b2) {
    __shared__ float sv[CCH * 20 * ROWF];   // 4 ch x 20 rows x 136 floats = 43.5KB
    __shared__ float sw[C1 * 25];           // [c][tap] = 3.2KB

    int tid = threadIdx.x;                  // 256
    int x0 = blockIdx.x * TX;               // 0 or 128
    int y0 = blockIdx.y * TY;
    int b  = blockIdx.z;

    // stage weights transposed: sw[c*25+t] = w2[t*32+c]
    for (int e = tid; e < C1 * 25; e += 256) {
        int c = e / 25, t = e % 25;
        sw[e] = w2[t * C1 + c];
    }

    int tx = tid & 31;                      // x-group: 4 outputs at x0+tx*4..+3
    int ty = tid >> 5;                      // y-group: 2 outputs at y0+ty*2, +1

    float acc[2][4];
    #pragma unroll
    for (int oy = 0; oy < 2; oy++)
        #pragma unroll
        for (int ox = 0; ox < 4; ox++) acc[oy][ox] = 0.f;

    for (int cb = 0; cb < C1; cb += CCH) {
        __syncthreads();   // previous chunk's compute done before overwrite
        // stage CCH planes, rows y0-2..y0+17, cols x0-2..x0+129 (zero halo)
        for (int e = tid; e < CCH * 20 * 132; e += 256) {
            int c   = e / (20 * 132);
            int rem = e % (20 * 132);
            int row = rem / 132;
            int x   = rem % 132;
            int gy = y0 + row - 2;
            int gx = x0 + x - 2;
            float v = 0.f;
            if (gy >= 0 && gy < HC && gx >= 0 && gx < WC)
                v = g_h1[((size_t)(b * C1 + cb + c) * HC + gy) * WC + gx];
            sv[(c * 20 + row) * ROWF + x] = v;
        }
        __syncthreads();

        #pragma unroll
        for (int c = 0; c < CCH; c++) {
            float wr[25];
            #pragma unroll
            for (int t = 0; t < 25; t++) wr[t] = sw[(cb + c) * 25 + t];

            #pragma unroll
            for (int r = 0; r < 6; r++) {
                const float4* rowp = (const float4*)&sv[(c * 20 + ty * 2 + r) * ROWF];
                float4 va = rowp[tx];
                float4 vb = rowp[tx + 1];
                float v[8] = {va.x, va.y, va.z, va.w, vb.x, vb.y, vb.z, vb.w};
                #pragma unroll
                for (int oy = 0; oy < 2; oy++) {
                    int ky = r - oy;
                    if (ky < 0 || ky > 4) continue;
                    #pragma unroll
                    for (int kx = 0; kx < 5; kx++) {
                        float w = wr[ky * 5 + kx];
                        #pragma unroll
                        for (int ox = 0; ox < 4; ox++)
                            acc[oy][ox] = fmaf(v[ox + kx], w, acc[oy][ox]);
                    }
                }
            }
        }
    }

    float bias = __ldg(b2);
    #pragma unroll
    for (int oy = 0; oy < 2; oy++) {
        int gy = y0 + ty * 2 + oy;
        #pragma unroll
        for (int ox = 0; ox < 4; ox++) {
            int gx = x0 + tx * 4 + ox;
            float z = acc[oy][ox] + bias;
            g_cms[((size_t)b * HC + gy) * WC + gx] = 1.f / (1.f + expf(-z));
        }
    }
}

// ============================================================
// 4a) 3x3 NMS + threshold -> global score buffer
// ============================================================
__global__ void __launch_bounds__(256) k_nms() {
    int i = blockIdx.x * blockDim.x + threadIdx.x;   // over BATCH*HC*WC
    if (i >= BATCH * HC * WC) return;
    int p = i & (HC * WC - 1);
    int b = i >> 16;
    int y = p >> 8, x = p & 255;
    const float* cm = g_cms + (size_t)b * HC * WC;
    float v = cm[p];
    float mx = v;
    #pragma unroll
    for (int dy = -1; dy <= 1; dy++) {
        int yy = y + dy;
        if (yy < 0 || yy >= HC) continue;
        #pragma unroll
        for (int dx = -1; dx <= 1; dx++) {
            int xx = x + dx;
            if (xx < 0 || xx >= WC) continue;
            mx = fmaxf(mx, cm[yy * WC + xx]);
        }
    }
    g_nms[i] = (v >= mx && v > 0.2f) ? v : -INFINITY;
}

// ============================================================
// 4b) exact top-32 per sample (jax tie-break: val desc, idx asc)
// ============================================================
__device__ __forceinline__ unsigned int f2ord(float v) {
    unsigned int u = __float_as_uint(v);
    return (u & 0x80000000u) ? ~u : (u | 0x80000000u);
}
__device__ __forceinline__ float ord2f(unsigned int u) {
    unsigned int bits = (u & 0x80000000u) ? (u ^ 0x80000000u) : ~u;
    return __uint_as_float(bits);
}
__device__ __forceinline__ unsigned long long mk_key(float v, unsigned p) {
    return ((unsigned long long)f2ord(v) << 32) |
           (unsigned long long)(0xFFFFFFFFu - p);
}

__global__ void __launch_bounds__(1024) k_topk() {
    int b = blockIdx.x;
    int t = threadIdx.x;                // 0..1023
    float* nms = g_nms + (size_t)b * HC * WC;

    unsigned long long mybest = 0;
    #pragma unroll 4
    for (int s = 0; s < 64; s++) {
        unsigned p = s * 1024 + t;
        unsigned long long key = mk_key(nms[p], p);
        if (key > mybest) mybest = key;
    }

    __shared__ unsigned long long warpbest[32];
    __shared__ unsigned long long winner;
    int lane = t & 31, wid = t >> 5;

    for (int k = 0; k < KP; k++) {
        unsigned long long v = mybest;
        #pragma unroll
        for (int off = 16; off > 0; off >>= 1) {
            unsigned long long o = __shfl_xor_sync(0xFFFFFFFFu, v, off);
            if (o > v) v = o;
        }
        if (lane == 0) warpbest[wid] = v;
        __syncthreads();
        if (t < 32) {
            unsigned long long bb = warpbest[t];
            #pragma unroll
            for (int off = 16; off > 0; off >>= 1) {
                unsigned long long o = __shfl_xor_sync(0xFFFFFFFFu, bb, off);
                if (o > bb) bb = o;
            }
            if (t == 0) winner = bb;
        }
        __syncthreads();
        unsigned long long wk = winner;
        unsigned int widx = 0xFFFFFFFFu - (unsigned int)(wk & 0xFFFFFFFFu);
        if (t == 0) {
            g_val[b * KP + k] = ord2f((unsigned int)(wk >> 32));
            g_idx[b * KP + k] = (int)widx;
        }
        if ((widx & 1023u) == (unsigned)t) {
            nms[widx] = -INFINITY;
            unsigned long long nb = 0;
            for (int s = 0; s < 64; s++) {
                unsigned p = s * 1024 + t;
                unsigned long long key = mk_key(nms[p], p);
                if (key > nb) nb = key;
            }
            mybest = nb;
        }
        __syncthreads();
    }
}

// ============================================================
// 5) integral refinement + centroid outputs
// ============================================================
__global__ void __launch_bounds__(512) k_refine(float* __restrict__ out) {
    int i = blockIdx.x * blockDim.x + threadIdx.x;   // 512
    if (i >= BATCH * KP) return;
    int b = i / KP;
    float v = g_val[i];
    int idx = g_idx[i];
    int valid = isfinite(v) ? 1 : 0;
    int py = idx >> 8, px = idx & 255;
    const float* cm = g_cms + (size_t)b * HC * WC;

    float gv = 1e-12f, sx = 0.f, sy = 0.f;
    #pragma unroll
    for (int dy = -2; dy <= 2; dy++) {
        int y = py + dy;
        if (y < 0 || y >= HC) continue;
        #pragma unroll
        for (int dx = -2; dx <= 2; dx++) {
            int x = px + dx;
            if (x < 0 || x >= WC) continue;
            float p = cm[y * WC + x];
            gv += p;
            sx += p * (float)dx;
            sy += p * (float)dy;
        }
    }
    float dxo = sx / gv, dyo = sy / gv;
    float cx = ((float)px + dxo) * 4.0f;   // CM_STRIDE/SCALE = 2/0.5
    float cy = ((float)py + dyo) * 4.0f;
    if (!valid) { cx = 80.f; cy = 80.f; }
    float cvv = valid ? v : 0.f;

    g_cx[i] = cx; g_cy[i] = cy; g_vld[i] = valid;
    out[OFF_OFFS + i * 2 + 0] = cx - 80.f;
    out[OFF_OFFS + i * 2 + 1] = cy - 80.f;
    out[OFF_VALS + i] = cvv;
    out[OFF_VALID + i] = valid ? 1.f : 0.f;
}

// ============================================================
// 6) 160x160 bilinear crops from the full image (extrap 0, valid mask)
// ============================================================
__global__ void __launch_bounds__(256) k_crop(const float* __restrict__ img,
                                              float* __restrict__ out) {
    int bk  = blockIdx.y;                               // 0..511
    int pix = blockIdx.x * blockDim.x + threadIdx.x;    // 0..25599
    if (pix >= CROPSZ * CROPSZ) return;
    float* o = out + (size_t)bk * CROPSZ * CROPSZ + pix;
    if (!g_vld[bk]) { *o = 0.f; return; }

    int b = bk / KP;
    float cx = g_cx[bk], cy = g_cy[bk];
    int yy = pix / CROPSZ, xx = pix % CROPSZ;
    float syf = cy - 79.5f + (float)yy;
    float sxf = cx - 79.5f + (float)xx;
    float y0 = floorf(syf), x0 = floorf(sxf);
    float wy = syf - y0,   wx = sxf - x0;
    int iy0 = min(max((int)y0, 0), H - 1);
    int iy1 = min(max((int)y0 + 1, 0), H - 1);
    int ix0 = min(max((int)x0, 0), W - 1);
    int ix1 = min(max((int)x0 + 1, 0), W - 1);
    const float* im = img + (size_t)b * H * W;
    float a  = __ldg(&im[(size_t)iy0 * W + ix0]);
    float bb = __ldg(&im[(size_t)iy0 * W + ix1]);
    float c  = __ldg(&im[(size_t)iy1 * W + ix0]);
    float d  = __ldg(&im[(size_t)iy1 * W + ix1]);
    float top = a * (1.f - wx) + bb * wx;
    float bot = c * (1.f - wx) + d * wx;
    float r = top * (1.f - wy) + bot * wy;
    bool inr = (syf >= 0.f) && (syf <= (float)(H - 1)) &&
               (sxf >= 0.f) && (sxf <= (float)(W - 1));
    *o = inr ? r : 0.f;
}

// ============================================================
extern "C" void kernel_launch(void* const* d_in, const int* in_sizes, int n_in,
                              void* d_out, int out_size) {
    const float* full = (const float*)d_in[0];
    const float* w1   = (const float*)d_in[1];
    const float* b1   = (const float*)d_in[2];
    const float* w2   = (const float*)d_in[3];
    const float* b2   = (const float*)d_in[4];
    float* out = (float*)d_out;

    int n;
    n = BATCH * H * WS;   k_resize_h<<<(n + 255) / 256, 256>>>(full);
    n = BATCH * HS * WS;  k_resize_v<<<(n + 255) / 256, 256>>>();
    n = BATCH * HC * WC;  k_conv1<<<(n + 255) / 256, 256>>>(w1, b1);
    k_conv2<<<dim3(WC / TX, HC / TY, BATCH), 256>>>(w2, b2);
    n = BATCH * HC * WC;  k_nms<<<(n + 255) / 256, 256>>>();
    k_topk<<<BATCH, 1024>>>();
    k_refine<<<1, 512>>>(out);
    k_crop<<<dim3((CROPSZ * CROPSZ + 255) / 256, BATCH * KP), 256>>>(full, out);
}